// round 13
// baseline (speedup 1.0000x reference)
#include <cuda_runtime.h>

typedef unsigned long long u64;
typedef unsigned int u32;

// ---- packed f32x2 helpers (Blackwell sm_100a) ----
__device__ __forceinline__ u64 pk2(float lo, float hi) {
    u64 r; asm("mov.b64 %0, {%1, %2};" : "=l"(r) : "f"(lo), "f"(hi)); return r;
}
__device__ __forceinline__ void upk2(u64 v, float& lo, float& hi) {
    asm("mov.b64 {%0, %1}, %2;" : "=f"(lo), "=f"(hi) : "l"(v));
}
__device__ __forceinline__ u64 fma2(u64 a, u64 b, u64 c) {
    u64 r; asm("fma.rn.f32x2 %0, %1, %2, %3;" : "=l"(r) : "l"(a), "l"(b), "l"(c)); return r;
}

#define PC5(v) ((((v)>>0)&1)+(((v)>>1)&1)+(((v)>>2)&1)+(((v)>>3)&1)+(((v)>>4)&1))

// 10-qubit register: wire w = flat-index bit (9-w).
// 1 element per warp; 32 lanes; 32 packed (re,im) amps per thread.
// XOR-skewed storage: register r (5 bits) holds the amp whose local bits are
//   y = r ^ lane  (all 5 local bits skewed by the 5 lane bits).
// Wire assignment alternates per layer (parity p = d&1):
//   p=0: local slot v <-> global bit v   (wire 9-v); lane slot u <-> bit 5+u (wire 4-u)
//   p=1: local slot v <-> global bit 5+v (wire 4-v); lane slot u <-> bit u   (wire 9-u)
// The full 5-bit lane<->local exchange is ONE shfl_xor per register (mask r).
//
// CZ ELIMINATION BY CONJUGATION: CZ = diag sign D. Pushing D through the
// tangent-form Givens gates (D G D^-1 = G with te -> sigma_i*sigma_j*te)
// makes even layers plain and odd layers sigma-signed; the final D dies in
// |amp|^2. For a gate on global bit t: sigma_i*sigma_j = (-1)^(b_{t-1}^b_{t+1}),
// split into a compile-time register-bit parity (RMASK) and a lane-bit parity
// folded into te's sign bit.

template<int K>
__device__ __forceinline__ void gate_slot(u64 (&st)[32], u64 tt, u64 nt) {
#pragma unroll
    for (int w = 0; w < 16; w++) {
        const int i  = ((w >> K) << (K + 1)) | (w & ((1 << K) - 1));
        const int j2 = i | (1 << K);
        const u64 a0 = st[i], a1 = st[j2];
        st[i]  = fma2(nt, a1, a0);   // a0 - te*a1
        st[j2] = fma2(tt, a0, a1);   // a1 + te*a0
    }
}

template<int K, int RMASK>
__device__ __forceinline__ void gate_slot_sig(u64 (&st)[32], u64 tt, u64 nt) {
#pragma unroll
    for (int w = 0; w < 16; w++) {
        const int i  = ((w >> K) << (K + 1)) | (w & ((1 << K) - 1));
        const int j2 = i | (1 << K);
        const int neg = PC5(i & RMASK) & 1;            // compile-time
        const u64 a0 = st[i], a1 = st[j2];
        if (neg) {
            st[i]  = fma2(tt, a1, a0);   // te negated for this pair
            st[j2] = fma2(nt, a0, a1);
        } else {
            st[i]  = fma2(nt, a1, a0);
            st[j2] = fma2(tt, a0, a1);
        }
    }
}

__device__ __forceinline__ void swap_fused(u64 (&st)[32]) {
#pragma unroll
    for (int r = 1; r < 32; r++)
        st[r] = __shfl_xor_sync(0xffffffffu, st[r], r);
}

__global__ __launch_bounds__(128, 4)
void qsim_kernel(const float* __restrict__ x,
                 const float* __restrict__ params,
                 const float* __restrict__ w_cls,
                 const float* __restrict__ b_cls,
                 float* __restrict__ out, int B)
{
    __shared__ float tsh[64], cwork[64], T2[64], wsh[160], bsh[16];
    __shared__ float Cprod_sh;
    const int tid = threadIdx.x;
    if (tid < 60) {
        float s, c;
        sincosf(params[tid] * 0.5f, &s, &c);
        tsh[tid] = s / c;          // tan(theta/2)
        cwork[tid] = c;
    }
    for (int k = tid; k < 160; k += 128) wsh[k] = w_cls[k];
    if (tid < 16) bsh[tid] = b_cls[tid];
    __syncthreads();
    // per-layer gate order: k=0..4 phase-1 slots, k=5..9 phase-2 slots
    if (tid < 60) {
        int d = tid / 10, k = tid % 10, p = d & 1;
        int wire;
        if (k < 5) wire = p ? 4 - k : 9 - k;
        else { int j = k - 5; wire = p ? 9 - j : 4 - j; }
        T2[tid] = tsh[d * 10 + wire];
    }
    if (tid == 0) {
        float pp = 1.0f;
        for (int k = 0; k < 60; k++) pp *= cwork[k];
        Cprod_sh = pp;             // deferred cos product
    }
    __syncthreads();
    const float Cprod = Cprod_sh;

    const int l    = tid & 31;                       // 5-bit lane
    const int elem = blockIdx.x * (blockDim.x >> 5) + (tid >> 5);
    if (elem >= B) return;

    // ---------- initial product state from RX layer (parity 0, skewed) ----------
    // lanes 0..9 compute one sincos each; broadcast packed (c,s).
    u64 cspack = 0;
    if (l < 10) {
        float s, c;
        sincosf(x[elem * 10 + l] * 0.5f, &s, &c);
        cspack = pk2(c, s);
    }
    float cx[10], sx[10];
#pragma unroll
    for (int q = 0; q < 10; q++) {
        u64 v = __shfl_sync(0xffffffffu, cspack, q);
        upk2(v, cx[q], sx[q]);
    }

    // lane product: lane slot u <-> bit 5+u <-> wire 4-u
    float lp = Cprod;
#pragma unroll
    for (int u = 0; u < 5; u++)
        lp *= ((l >> u) & 1) ? sx[4 - u] : cx[4 - u];

    // skew-aware per-level factors: reg bit v=1 means amp bit y_v = 1^l_v
    float fhi[5], flo[5];
#pragma unroll
    for (int v = 0; v < 5; v++) {
        const bool lb = (l >> v) & 1;
        fhi[v] = lb ? cx[9 - v] : sx[9 - v];
        flo[v] = lb ? sx[9 - v] : cx[9 - v];
    }

    float pr[32];
    pr[0] = lp;
#pragma unroll
    for (int v = 0; v < 5; v++) {
#pragma unroll
        for (int i = 0; i < 16; i++) {
            if (i < (1 << v)) {
                pr[i | (1 << v)] = pr[i] * fhi[v];
                pr[i]            = pr[i] * flo[v];
            }
        }
    }

    // phase (-i)^popc(b): popc(b) = popc(r) + 2*(popc(l) - popc(r&l))
    // per-reg extra sign = parity(r&l) ^ parity(l), via 32-bit table
    u32 Tpar = 0;
    if (l & 1)  Tpar ^= 0xAAAAAAAAu;
    if (l & 2)  Tpar ^= 0xCCCCCCCCu;
    if (l & 4)  Tpar ^= 0xF0F0F0F0u;
    if (l & 8)  Tpar ^= 0xFF00FF00u;
    if (l & 16) Tpar ^= 0xFFFF0000u;
    if (__popc(l) & 1) Tpar ^= 0xFFFFFFFFu;

    u64 st[32];
#pragma unroll
    for (int r = 0; r < 32; r++) {
        const int C = PC5(r);                          // compile-time
        const u32 e31 = ((Tpar >> r) & 1u) << 31;
        const u32 bits = __float_as_uint(pr[r]);
        if ((C & 1) == 0) {
            const u32 reb = bits ^ e31 ^ ((u32)((C >> 1) & 1) << 31);
            st[r] = pk2(__uint_as_float(reb), 0.0f);
        } else {
            const u32 imb = bits ^ e31 ^ ((u32)(((C >> 1) & 1) ^ 1) << 31);
            st[r] = pk2(0.0f, __uint_as_float(imb));
        }
    }

    // ---------- lane-dependent sign bits ----------
    const u32 l0 = (l >> 0) & 1, l1 = (l >> 1) & 1, l2 = (l >> 2) & 1,
              l3 = (l >> 3) & 1, l4 = (l >> 4) & 1;
    // even layers: skew sign only
    const u32 SGE[5] = { l0 << 31, l1 << 31, l2 << 31, l3 << 31, l4 << 31 };
    // odd layers, phase 1 (p=1: slot k gates global bit 5+k; neighbors b4+k, b6+k)
    const u32 O1[5] = { (l0 ^ l1 ^ l4) << 31,   // k=0: skew l0 ^ lane(b4=l4) ^ lane(b6=y1->l1); RMASK r1
                        (l0 ^ l1 ^ l2) << 31,   // k=1: b5(y0),b7(y2): RMASK r0^r2
                        (l1 ^ l2 ^ l3) << 31,   // k=2: b6,b8: RMASK r1^r3
                        (l2 ^ l3 ^ l4) << 31,   // k=3: b7,b9: RMASK r2^r4
                        (l3 ^ l4) << 31 };      // k=4 (t=9): b8 only: RMASK r3
    // odd layers, phase 2 (p=0: slot k gates global bit k; neighbors b_{k-1}, b_{k+1})
    const u32 O2[5] = { (l0 ^ l1) << 31,        // k=0 (t=0): b1 only: RMASK r1
                        (l0 ^ l1 ^ l2) << 31,   // k=1: RMASK r0^r2
                        (l1 ^ l2 ^ l3) << 31,   // k=2: RMASK r1^r3
                        (l2 ^ l3 ^ l4) << 31,   // k=3: RMASK r2^r4
                        (l0 ^ l3 ^ l4) << 31 }; // k=4: b3(y3), b5(lane l0): RMASK r3

#define MKCOEF(tval, sgn, TT, NT) do { \
        const float _te = __uint_as_float(__float_as_uint(tval) ^ (sgn)); \
        TT = pk2(_te, _te); NT = pk2(-_te, -_te); } while (0)

    // ---------- 6 variational layers (CZ folded into odd-layer signs) ----------
#pragma unroll 1
    for (int dd = 0; dd < 3; dd++) {
        const float* Te = T2 + (2 * dd) * 10;
        const float* To = T2 + (2 * dd + 1) * 10;
        u64 tt, nt;

        // ======== even layer 2*dd (plain skew signs) ========
        MKCOEF(Te[0], SGE[0], tt, nt); gate_slot<0>(st, tt, nt);
        MKCOEF(Te[1], SGE[1], tt, nt); gate_slot<1>(st, tt, nt);
        MKCOEF(Te[2], SGE[2], tt, nt); gate_slot<2>(st, tt, nt);
        MKCOEF(Te[3], SGE[3], tt, nt); gate_slot<3>(st, tt, nt);
        MKCOEF(Te[4], SGE[4], tt, nt); gate_slot<4>(st, tt, nt);
        swap_fused(st);
        MKCOEF(Te[5], SGE[0], tt, nt); gate_slot<0>(st, tt, nt);
        MKCOEF(Te[6], SGE[1], tt, nt); gate_slot<1>(st, tt, nt);
        MKCOEF(Te[7], SGE[2], tt, nt); gate_slot<2>(st, tt, nt);
        MKCOEF(Te[8], SGE[3], tt, nt); gate_slot<3>(st, tt, nt);
        MKCOEF(Te[9], SGE[4], tt, nt); gate_slot<4>(st, tt, nt);

        // ======== odd layer 2*dd+1 (CZ-conjugated signs) ========
        MKCOEF(To[0], O1[0], tt, nt); gate_slot_sig<0, 0x02>(st, tt, nt);
        MKCOEF(To[1], O1[1], tt, nt); gate_slot_sig<1, 0x05>(st, tt, nt);
        MKCOEF(To[2], O1[2], tt, nt); gate_slot_sig<2, 0x0A>(st, tt, nt);
        MKCOEF(To[3], O1[3], tt, nt); gate_slot_sig<3, 0x14>(st, tt, nt);
        MKCOEF(To[4], O1[4], tt, nt); gate_slot_sig<4, 0x08>(st, tt, nt);
        swap_fused(st);
        MKCOEF(To[5], O2[0], tt, nt); gate_slot_sig<0, 0x02>(st, tt, nt);
        MKCOEF(To[6], O2[1], tt, nt); gate_slot_sig<1, 0x05>(st, tt, nt);
        MKCOEF(To[7], O2[2], tt, nt); gate_slot_sig<2, 0x0A>(st, tt, nt);
        MKCOEF(To[8], O2[3], tt, nt); gate_slot_sig<3, 0x14>(st, tt, nt);
        MKCOEF(To[9], O2[4], tt, nt); gate_slot_sig<4, 0x08>(st, tt, nt);
    }
#undef MKCOEF

    // ---------- probabilities and <Z_q> (final layout = parity 0, skewed) ----------
    float t_all = 0.0f, sb[5] = {0, 0, 0, 0, 0};
#pragma unroll
    for (int r = 0; r < 32; r++) {
        float re, im; upk2(st[r], re, im);
        const float p2 = fmaf(im, im, re * re);
        t_all += p2;
#pragma unroll
        for (int v = 0; v < 5; v++)
            if (r & (1 << v)) sb[v] += p2;
    }
    float ex[10];
#pragma unroll
    for (int q2 = 0; q2 < 5; q2++)                    // lane slots: bit 5+u -> wire 4-u
        ex[q2] = ((l >> (4 - q2)) & 1) ? -t_all : t_all;
#pragma unroll
    for (int v = 0; v < 5; v++) {                     // skewed local slots: bit v -> wire 9-v
        const float e = t_all - 2.0f * sb[v];
        ex[9 - v] = ((l >> v) & 1) ? -e : e;
    }

    // reduce across all 32 lanes of this element
#pragma unroll
    for (int m = 16; m >= 1; m >>= 1) {
#pragma unroll
        for (int q2 = 0; q2 < 10; q2++)
            ex[q2] += __shfl_xor_sync(0xffffffffu, ex[q2], m);
    }

    // ---------- classifier head: lanes 0..15 emit one class each ----------
    if (l < 16) {
        float acc = bsh[l];
#pragma unroll
        for (int q2 = 0; q2 < 10; q2++)
            acc = fmaf(ex[q2], wsh[l * 10 + q2], acc);
        out[elem * 16 + l] = acc;
    }
}

extern "C" void kernel_launch(void* const* d_in, const int* in_sizes, int n_in,
                              void* d_out, int out_size)
{
    const float* x      = (const float*)d_in[0];  // (B, 10)
    const float* params = (const float*)d_in[1];  // (6, 10)
    const float* w_cls  = (const float*)d_in[2];  // (16, 10)
    const float* b_cls  = (const float*)d_in[3];  // (16,)
    float* out = (float*)d_out;

    const int B = in_sizes[0] / 10;
    const int elems_per_block = 4;                // 4 warps x 1 element
    const int blocks = (B + elems_per_block - 1) / elems_per_block;
    qsim_kernel<<<blocks, 128>>>(x, params, w_cls, b_cls, out, B);
}

// round 14
// speedup vs baseline: 1.1812x; 1.1812x over previous
#include <cuda_runtime.h>

typedef unsigned long long u64;
typedef unsigned int u32;

// ---- packed f32x2 helpers (Blackwell sm_100a) ----
__device__ __forceinline__ u64 pk2(float lo, float hi) {
    u64 r; asm("mov.b64 %0, {%1, %2};" : "=l"(r) : "f"(lo), "f"(hi)); return r;
}
__device__ __forceinline__ void upk2(u64 v, float& lo, float& hi) {
    asm("mov.b64 {%0, %1}, %2;" : "=f"(lo), "=f"(hi) : "l"(v));
}
__device__ __forceinline__ u64 fma2(u64 a, u64 b, u64 c) {
    u64 r; asm("fma.rn.f32x2 %0, %1, %2, %3;" : "=l"(r) : "l"(a), "l"(b), "l"(c)); return r;
}
__device__ __forceinline__ u64 mul2(u64 a, u64 b) {
    u64 r; asm("mul.rn.f32x2 %0, %1, %2;" : "=l"(r) : "l"(a), "l"(b)); return r;
}
// packed complex multiply: z * w, with w pre-split as wr2=(re,re), wi2=(-im,im).
// swap(z) is a register rename (free).
__device__ __forceinline__ u64 cmul(u64 z, u64 wr2, u64 wi2) {
    float zr, zi; upk2(z, zr, zi);
    return fma2(wi2, pk2(zi, zr), mul2(wr2, z));
}

#define PC6(v) ((((v)>>0)&1)+(((v)>>1)&1)+(((v)>>2)&1)+(((v)>>3)&1)+(((v)>>4)&1)+(((v)>>5)&1))

// 10-qubit register: wire w = flat-index bit (9-w); bit g <-> wire 9-g.
// 2 elements per warp; 16 lanes (l = lane&15) per element; 64 amps/thread.
// XOR-skewed storage: register r holds the amp whose local-slot bits are
//   y_v = r_v ^ l_v (v<4); y_4 = r_4; y_5 = r_5.
// Parity p layouts:
//   p=0: local slot v <-> bit v ; lane slot u <-> bit 6+u
//   p=1: local slot v<4 <-> bit 6+v ; slots 4,5 <-> bits 4,5 ; lane u <-> bit u
// The 4-bit lane<->local exchange is ONE shfl_xor per register (mask r&15).
//
// LAYER-0 FUSION: state is a product state until the first CZ, so the d=0 RY
// layer is folded into the per-wire init vectors u_w = RY_tan(t0)RX(x)|0> =
// (c + i t0 s, t0 c - i s) (cos factors deferred into Cprod). Amps are built
// as complex tensor products — the (-i)^popc phase machinery disappears.
// CZ conjugation for the remaining 5 layers:
//   final = L5^s L4 L3^s L2 L1^s psi0   (all CZ diagonals annihilate exactly)
// Odd layers (d=1,3,5) enter parity 0 and carry sigma signs; even plain.
// Gate on bit t: sigma_i*sigma_j = (-1)^(b_{t-1}^b_{t+1}), split into a
// compile-time register-bit parity (RMASK) + lane parity in te's sign bit.

template<int K>
__device__ __forceinline__ void gate_slot(u64 (&st)[64], u64 tt, u64 nt) {
#pragma unroll
    for (int w = 0; w < 32; w++) {
        const int i  = ((w >> K) << (K + 1)) | (w & ((1 << K) - 1));
        const int j2 = i | (1 << K);
        const u64 a0 = st[i], a1 = st[j2];
        st[i]  = fma2(nt, a1, a0);   // a0 - te*a1
        st[j2] = fma2(tt, a0, a1);   // a1 + te*a0
    }
}

template<int K, int RMASK>
__device__ __forceinline__ void gate_slot_sig(u64 (&st)[64], u64 tt, u64 nt) {
#pragma unroll
    for (int w = 0; w < 32; w++) {
        const int i  = ((w >> K) << (K + 1)) | (w & ((1 << K) - 1));
        const int j2 = i | (1 << K);
        const int neg = PC6(i & RMASK) & 1;            // compile-time
        const u64 a0 = st[i], a1 = st[j2];
        if (neg) {
            st[i]  = fma2(tt, a1, a0);   // te negated for this pair
            st[j2] = fma2(nt, a0, a1);
        } else {
            st[i]  = fma2(nt, a1, a0);
            st[j2] = fma2(tt, a0, a1);
        }
    }
}

__device__ __forceinline__ void swap_fused(u64 (&st)[64]) {
#pragma unroll
    for (int r = 0; r < 64; r++) {
        const int m = r & 15;
        if (m)
            st[r] = __shfl_xor_sync(0xffffffffu, st[r], m);
    }
}

__global__ __launch_bounds__(128, 3)
void qsim_kernel(const float* __restrict__ x,
                 const float* __restrict__ params,
                 const float* __restrict__ w_cls,
                 const float* __restrict__ b_cls,
                 float* __restrict__ out, int B)
{
    __shared__ float tsh[64], cwork[64], T2[64], wsh[160], bsh[16];
    __shared__ float Cprod_sh;
    const int tid = threadIdx.x;
    if (tid < 60) {
        float s, c;
        sincosf(params[tid] * 0.5f, &s, &c);
        tsh[tid] = s / c;          // tan(theta/2)
        cwork[tid] = c;
    }
    for (int k = tid; k < 160; k += 128) wsh[k] = w_cls[k];
    if (tid < 16) bsh[tid] = b_cls[tid];
    __syncthreads();
    // T2 rows 0..4 <-> layers d=1..5; entry parity pe(d) = (d+1)&1
    // k=0..5 phase-1 slots, k=6..9 phase-2 slots
    if (tid < 50) {
        int row = tid / 10, k = tid % 10;
        int d = row + 1, pe = (d + 1) & 1;
        int wire;
        if (k < 6) wire = pe ? ((k < 4) ? 3 - k : 9 - k) : 9 - k;
        else { int j = k - 6; wire = pe ? 9 - j : 3 - j; }
        T2[tid] = tsh[d * 10 + wire];
    }
    if (tid == 0) {
        float pp = 1.0f;
        for (int k = 0; k < 60; k++) pp *= cwork[k];
        Cprod_sh = pp;             // deferred cos product (incl. layer 0)
    }
    __syncthreads();
    const float Cprod = Cprod_sh;

    const int lane = tid & 31;
    const int l    = lane & 15;
    const int half = lane >> 4;
    const int elem = (blockIdx.x * (blockDim.x >> 5) + (tid >> 5)) * 2 + half;
    if (elem >= B) return;

    // ---------- init: product of u_w = RY_tan(t0_w) RX(x_w) |0>  ----------
    // lanes 0..9 of each half compute one sincos; broadcast packed (c,s).
    u64 cspack = 0;
    if (l < 10) {
        float s, c;
        sincosf(x[elem * 10 + l] * 0.5f, &s, &c);
        cspack = pk2(c, s);
    }
    // per-wire complex 2-vectors: u_w[0] = (c, t0*s), u_w[1] = (t0*c, -s)
    float re0[10], im0[10], re1[10], im1[10];
#pragma unroll
    for (int q = 0; q < 10; q++) {
        float c, s;
        upk2(__shfl_sync(0xffffffffu, cspack, (lane & 16) + q), c, s);
        const float t0 = tsh[q];               // layer-0 tangent, wire q
        re0[q] = c;        im0[q] = t0 * s;
        re1[q] = t0 * c;   im1[q] = -s;
    }

    // lane product over bits 6..9 (p=0: bit 6+u = l_u, wire 3-u), scaled by Cprod
    const int l0 = (l >> 0) & 1, l1 = (l >> 1) & 1, l2 = (l >> 2) & 1, l3 = (l >> 3) & 1;
    u64 z = pk2(l0 ? re1[3] : re0[3], l0 ? im1[3] : im0[3]);
    {
        const int lb[3] = { l1, l2, l3 };
#pragma unroll
        for (int u = 1; u < 4; u++) {
            const int w = 3 - u;
            const float wre = lb[u - 1] ? re1[w] : re0[w];
            const float wim = lb[u - 1] ? im1[w] : im0[w];
            z = cmul(z, pk2(wre, wre), pk2(-wim, wim));
        }
        z = mul2(z, pk2(Cprod, Cprod));
    }

    // per-slot complex factors (skew-aware for v<4): slot v <-> bit v, wire 9-v
    u64 flor2[6], floi2[6], fhir2[6], fhii2[6];
#pragma unroll
    for (int v = 0; v < 6; v++) {
        const int w = 9 - v;
        const int lb = (v < 4) ? ((l >> v) & 1) : 0;
        const float lre = lb ? re1[w] : re0[w], lim = lb ? im1[w] : im0[w];
        const float hre = lb ? re0[w] : re1[w], him = lb ? im0[w] : im1[w];
        flor2[v] = pk2(lre, lre); floi2[v] = pk2(-lim, lim);
        fhir2[v] = pk2(hre, hre); fhii2[v] = pk2(-him, him);
    }

    // recursive complex tensor-product build (in place)
    u64 st[64];
    st[0] = z;
#pragma unroll
    for (int v = 0; v < 6; v++) {
#pragma unroll
        for (int i = 0; i < 32; i++) {
            if (i < (1 << v)) {
                st[i | (1 << v)] = cmul(st[i], fhir2[v], fhii2[v]);
                st[i]            = cmul(st[i], flor2[v], floi2[v]);
            }
        }
    }

    // ---------- sign bits ----------
    const u32 SGE[4] = { (u32)l0 << 31, (u32)l1 << 31, (u32)l2 << 31, (u32)l3 << 31 };
    const u32 SA  = (u32)(l0 ^ l1) << 31;        // odd ph1 v=0 / ph2 k=0
    const u32 SB  = (u32)(l0 ^ l1 ^ l2) << 31;   // v=1 / k=1
    const u32 SC  = (u32)(l1 ^ l2 ^ l3) << 31;   // v=2 / k=2
    const u32 SD  = (u32)(l2 ^ l3) << 31;        // v=3 / k=3
    const u32 S4o = (u32)l3 << 31;               // odd ph1 v=4
    const u32 S5o = (u32)l0 << 31;               // odd ph1 v=5

#define MKCOEF(tval, sgn, TT, NT) do { \
        const float _te = __uint_as_float(__float_as_uint(tval) ^ (sgn)); \
        TT = pk2(_te, _te); NT = pk2(-_te, -_te); } while (0)

    // ---------- 5 layers: d=1,3,5 sigma'd (pe=0); d=2,4 plain (pe=1) ----------
#pragma unroll 1
    for (int dd = 0; dd < 3; dd++) {
        const float* To = T2 + (2 * dd) * 10;    // odd layer d=2dd+1
        u64 tt, nt;

        // odd layer, phase 1 (p=0 map: slot v gates bit v)
        MKCOEF(To[0], SA,  tt, nt); gate_slot_sig<0, 0x02>(st, tt, nt); // b1
        MKCOEF(To[1], SB,  tt, nt); gate_slot_sig<1, 0x05>(st, tt, nt); // b0^b2
        MKCOEF(To[2], SC,  tt, nt); gate_slot_sig<2, 0x0A>(st, tt, nt); // b1^b3
        MKCOEF(To[3], SD,  tt, nt); gate_slot_sig<3, 0x14>(st, tt, nt); // b2^b4
        MKCOEF(To[4], S4o, tt, nt); gate_slot_sig<4, 0x28>(st, tt, nt); // b3^b5
        MKCOEF(To[5], S5o, tt, nt); gate_slot_sig<5, 0x10>(st, tt, nt); // b4^b6
        swap_fused(st);
        // odd layer, phase 2 (p=1 map: slot k gates bit 6+k)
        MKCOEF(To[6], SA, tt, nt); gate_slot_sig<0, 0x22>(st, tt, nt);  // b5^b7
        MKCOEF(To[7], SB, tt, nt); gate_slot_sig<1, 0x05>(st, tt, nt);  // b6^b8
        MKCOEF(To[8], SC, tt, nt); gate_slot_sig<2, 0x0A>(st, tt, nt);  // b7^b9
        MKCOEF(To[9], SD, tt, nt); gate_slot_sig<3, 0x04>(st, tt, nt);  // b8

        if (dd < 2) {
            const float* Te = T2 + (2 * dd + 1) * 10;   // even layer d=2dd+2
            // even layer (pe=1), phase 1: skew signs only
            MKCOEF(Te[0], SGE[0], tt, nt); gate_slot<0>(st, tt, nt);
            MKCOEF(Te[1], SGE[1], tt, nt); gate_slot<1>(st, tt, nt);
            MKCOEF(Te[2], SGE[2], tt, nt); gate_slot<2>(st, tt, nt);
            MKCOEF(Te[3], SGE[3], tt, nt); gate_slot<3>(st, tt, nt);
            MKCOEF(Te[4], 0u,     tt, nt); gate_slot<4>(st, tt, nt);
            MKCOEF(Te[5], 0u,     tt, nt); gate_slot<5>(st, tt, nt);
            swap_fused(st);
            MKCOEF(Te[6], SGE[0], tt, nt); gate_slot<0>(st, tt, nt);
            MKCOEF(Te[7], SGE[1], tt, nt); gate_slot<1>(st, tt, nt);
            MKCOEF(Te[8], SGE[2], tt, nt); gate_slot<2>(st, tt, nt);
            MKCOEF(Te[9], SGE[3], tt, nt); gate_slot<3>(st, tt, nt);
        }
    }
#undef MKCOEF

    // ---------- probabilities and <Z_q> (exit layout = parity 1, skewed) ----------
    float t_all = 0.0f, tb[6] = {0, 0, 0, 0, 0, 0};
#pragma unroll
    for (int r = 0; r < 64; r++) {
        float re, im; upk2(st[r], re, im);
        const float p2 = fmaf(im, im, re * re);
        t_all += p2;
#pragma unroll
        for (int v = 0; v < 6; v++)
            if (r & (1 << v)) tb[v] += p2;
    }
    float ex[10];
    // p=1: bit u = l_u -> wire 9-u
    ex[9] = l0 ? -t_all : t_all;
    ex[8] = l1 ? -t_all : t_all;
    ex[7] = l2 ? -t_all : t_all;
    ex[6] = l3 ? -t_all : t_all;
    // bits 4,5 = r4, r5 -> wires 5, 4
    ex[5] = t_all - 2.0f * tb[4];
    ex[4] = t_all - 2.0f * tb[5];
    // bits 6+k = r_k ^ l_k -> wires 3-k
#pragma unroll
    for (int k = 0; k < 4; k++) {
        const float e = t_all - 2.0f * tb[k];
        ex[3 - k] = ((l >> k) & 1) ? -e : e;
    }

    // reduce across the 16 lanes of this element
#pragma unroll
    for (int m = 8; m >= 1; m >>= 1) {
#pragma unroll
        for (int q2 = 0; q2 < 10; q2++)
            ex[q2] += __shfl_xor_sync(0xffffffffu, ex[q2], m);
    }

    // ---------- classifier head: each of 16 lanes emits one class ----------
    {
        float acc = bsh[l];
#pragma unroll
        for (int q2 = 0; q2 < 10; q2++)
            acc = fmaf(ex[q2], wsh[l * 10 + q2], acc);
        out[elem * 16 + l] = acc;
    }
}

extern "C" void kernel_launch(void* const* d_in, const int* in_sizes, int n_in,
                              void* d_out, int out_size)
{
    const float* x      = (const float*)d_in[0];  // (B, 10)
    const float* params = (const float*)d_in[1];  // (6, 10)
    const float* w_cls  = (const float*)d_in[2];  // (16, 10)
    const float* b_cls  = (const float*)d_in[3];  // (16,)
    float* out = (float*)d_out;

    const int B = in_sizes[0] / 10;
    const int elems_per_block = 8;                // 4 warps x 2 elements
    const int blocks = (B + elems_per_block - 1) / elems_per_block;
    qsim_kernel<<<blocks, 128>>>(x, params, w_cls, b_cls, out, B);
}

// round 15
// speedup vs baseline: 1.2083x; 1.0230x over previous
#include <cuda_runtime.h>

typedef unsigned long long u64;
typedef unsigned int u32;

// ---- packed f32x2 helpers (Blackwell sm_100a) ----
__device__ __forceinline__ u64 pk2(float lo, float hi) {
    u64 r; asm("mov.b64 %0, {%1, %2};" : "=l"(r) : "f"(lo), "f"(hi)); return r;
}
__device__ __forceinline__ void upk2(u64 v, float& lo, float& hi) {
    asm("mov.b64 {%0, %1}, %2;" : "=f"(lo), "=f"(hi) : "l"(v));
}
__device__ __forceinline__ u64 fma2(u64 a, u64 b, u64 c) {
    u64 r; asm("fma.rn.f32x2 %0, %1, %2, %3;" : "=l"(r) : "l"(a), "l"(b), "l"(c)); return r;
}
__device__ __forceinline__ u64 mul2(u64 a, u64 b) {
    u64 r; asm("mul.rn.f32x2 %0, %1, %2;" : "=l"(r) : "l"(a), "l"(b)); return r;
}
__device__ __forceinline__ u64 add2(u64 a, u64 b) {
    u64 r; asm("add.rn.f32x2 %0, %1, %2;" : "=l"(r) : "l"(a), "l"(b)); return r;
}
// packed complex multiply: z * w, with w pre-split as wr2=(re,re), wi2=(-im,im).
__device__ __forceinline__ u64 cmul(u64 z, u64 wr2, u64 wi2) {
    float zr, zi; upk2(z, zr, zi);
    return fma2(wi2, pk2(zi, zr), mul2(wr2, z));
}

#define PC6(v) ((((v)>>0)&1)+(((v)>>1)&1)+(((v)>>2)&1)+(((v)>>3)&1)+(((v)>>4)&1)+(((v)>>5)&1))

// 10-qubit register: wire w = flat-index bit (9-w); bit g <-> wire 9-g.
// 2 elements per warp; 16 lanes (l = lane&15) per element; 64 amps/thread.
// XOR-skewed storage: y_v = r_v ^ l_v (v<4); y_4 = r_4; y_5 = r_5.
// Parity p layouts:
//   p=0: local slot v <-> bit v ; lane slot u <-> bit 6+u
//   p=1: local slot v<4 <-> bit 6+v ; slots 4,5 <-> bits 4,5 ; lane u <-> bit u
// 4-bit lane<->local exchange = ONE shfl_xor per register (mask r&15).
//
// LAYER-0 FUSION: d=0 RY folded into init vectors u_w = RY_tan RX |0>.
// CZ conjugation: final = (D) L5^s L4 L3^s L2 L1^s psi0; outer D dies in probs.
// LAYER-5 FUSION (this round): L5^s folded into the observables:
//   ex_w = cos(t5_w) <Z_w> - sin(t5_w) <sigma X_w>     on the post-L4 state,
// where sigma_i*sigma_j = (-1)^(b_{t-1}^b_{t+1}) splits into a compile-time
// register parity (RMASK -> pos/neg accumulators) and a lane parity folded
// into sin's sign. X is 0<->1 symmetric so the skew sign drops out.

template<int K>
__device__ __forceinline__ void gate_slot(u64 (&st)[64], u64 tt, u64 nt) {
#pragma unroll
    for (int w = 0; w < 32; w++) {
        const int i  = ((w >> K) << (K + 1)) | (w & ((1 << K) - 1));
        const int j2 = i | (1 << K);
        const u64 a0 = st[i], a1 = st[j2];
        st[i]  = fma2(nt, a1, a0);   // a0 - te*a1
        st[j2] = fma2(tt, a0, a1);   // a1 + te*a0
    }
}

template<int K, int RMASK>
__device__ __forceinline__ void gate_slot_sig(u64 (&st)[64], u64 tt, u64 nt) {
#pragma unroll
    for (int w = 0; w < 32; w++) {
        const int i  = ((w >> K) << (K + 1)) | (w & ((1 << K) - 1));
        const int j2 = i | (1 << K);
        const int neg = PC6(i & RMASK) & 1;            // compile-time
        const u64 a0 = st[i], a1 = st[j2];
        if (neg) {
            st[i]  = fma2(tt, a1, a0);
            st[j2] = fma2(nt, a0, a1);
        } else {
            st[i]  = fma2(nt, a1, a0);
            st[j2] = fma2(tt, a0, a1);
        }
    }
}

// X-expectation partial for local slot K with sigma register-parity RMASK:
// returns sum_pairs (+/-)(re_i*re_j + im_i*im_j) for this thread.
template<int K, int RMASK>
__device__ __forceinline__ float xslot(const u64 (&st)[64]) {
    u64 xp = 0ull, xn = 0ull;     // bit pattern 0 == packed (0.0f, 0.0f)
#pragma unroll
    for (int w = 0; w < 32; w++) {
        const int i  = ((w >> K) << (K + 1)) | (w & ((1 << K) - 1));
        const int j2 = i | (1 << K);
        if (PC6(i & RMASK) & 1) xn = fma2(st[i], st[j2], xn);
        else                    xp = fma2(st[i], st[j2], xp);
    }
    float pl, ph, nl, nh; upk2(xp, pl, ph); upk2(xn, nl, nh);
    return (pl + ph) - (nl + nh);
}

__device__ __forceinline__ void swap_fused(u64 (&st)[64]) {
#pragma unroll
    for (int r = 0; r < 64; r++) {
        const int m = r & 15;
        if (m)
            st[r] = __shfl_xor_sync(0xffffffffu, st[r], m);
    }
}

__device__ __forceinline__ float sgnf(float f, u32 par) {
    return __uint_as_float(__float_as_uint(f) ^ (par << 31));
}

__global__ __launch_bounds__(128, 3)
void qsim_kernel(const float* __restrict__ x,
                 const float* __restrict__ params,
                 const float* __restrict__ w_cls,
                 const float* __restrict__ b_cls,
                 float* __restrict__ out, int B)
{
    __shared__ float tsh[64], cwork[64], T2[48], wsh[160], bsh[16];
    __shared__ float c5sh[10], s5sh[10];
    __shared__ float Cprod_sh;
    const int tid = threadIdx.x;
    if (tid < 60) {
        float s, c;
        sincosf(params[tid] * 0.5f, &s, &c);
        tsh[tid] = s / c;          // tan(theta/2)
        cwork[tid] = c;
    }
    if (tid >= 96 && tid < 106) {  // layer-5 FULL-angle coefficients
        const int w = tid - 96;
        float s, c;
        sincosf(params[50 + w], &s, &c);
        c5sh[w] = c;
        s5sh[w] = 2.0f * s;        // X cross-terms carry the factor 2
    }
    for (int k = tid; k < 160; k += 128) wsh[k] = w_cls[k];
    if (tid < 16) bsh[tid] = b_cls[tid];
    __syncthreads();
    // T2 rows 0..3 <-> layers d=1..4; entry parity pe(d) = (d+1)&1
    if (tid < 40) {
        int row = tid / 10, k = tid % 10;
        int d = row + 1, pe = (d + 1) & 1;
        int wire;
        if (k < 6) wire = pe ? ((k < 4) ? 3 - k : 9 - k) : 9 - k;
        else { int j = k - 6; wire = pe ? 9 - j : 3 - j; }
        T2[tid] = tsh[d * 10 + wire];
    }
    if (tid == 0) {
        float pp = 1.0f;
        for (int k = 0; k < 50; k++) pp *= cwork[k];   // layers 0..4 only
        Cprod_sh = pp;
    }
    __syncthreads();
    const float Cprod = Cprod_sh;

    const int lane = tid & 31;
    const int l    = lane & 15;
    const int half = lane >> 4;
    const int elem = (blockIdx.x * (blockDim.x >> 5) + (tid >> 5)) * 2 + half;
    if (elem >= B) return;

    // ---------- init: product of u_w = RY_tan(t0_w) RX(x_w) |0>  ----------
    u64 cspack = 0;
    if (l < 10) {
        float s, c;
        sincosf(x[elem * 10 + l] * 0.5f, &s, &c);
        cspack = pk2(c, s);
    }
    float re0[10], im0[10], re1[10], im1[10];
#pragma unroll
    for (int q = 0; q < 10; q++) {
        float c, s;
        upk2(__shfl_sync(0xffffffffu, cspack, (lane & 16) + q), c, s);
        const float t0 = tsh[q];
        re0[q] = c;        im0[q] = t0 * s;
        re1[q] = t0 * c;   im1[q] = -s;
    }

    // lane product over bits 6..9 (p=0: bit 6+u = l_u, wire 3-u), scaled by Cprod
    const int l0 = (l >> 0) & 1, l1 = (l >> 1) & 1, l2 = (l >> 2) & 1, l3 = (l >> 3) & 1;
    u64 z = pk2(l0 ? re1[3] : re0[3], l0 ? im1[3] : im0[3]);
    {
        const int lb[3] = { l1, l2, l3 };
#pragma unroll
        for (int u = 1; u < 4; u++) {
            const int w = 3 - u;
            const float wre = lb[u - 1] ? re1[w] : re0[w];
            const float wim = lb[u - 1] ? im1[w] : im0[w];
            z = cmul(z, pk2(wre, wre), pk2(-wim, wim));
        }
        z = mul2(z, pk2(Cprod, Cprod));
    }

    // per-slot complex factors (skew-aware for v<4): slot v <-> bit v, wire 9-v
    u64 flor2[6], floi2[6], fhir2[6], fhii2[6];
#pragma unroll
    for (int v = 0; v < 6; v++) {
        const int w = 9 - v;
        const int lb = (v < 4) ? ((l >> v) & 1) : 0;
        const float lre = lb ? re1[w] : re0[w], lim = lb ? im1[w] : im0[w];
        const float hre = lb ? re0[w] : re1[w], him = lb ? im0[w] : im1[w];
        flor2[v] = pk2(lre, lre); floi2[v] = pk2(-lim, lim);
        fhir2[v] = pk2(hre, hre); fhii2[v] = pk2(-him, him);
    }

    // recursive complex tensor-product build (in place)
    u64 st[64];
    st[0] = z;
#pragma unroll
    for (int v = 0; v < 6; v++) {
#pragma unroll
        for (int i = 0; i < 32; i++) {
            if (i < (1 << v)) {
                st[i | (1 << v)] = cmul(st[i], fhir2[v], fhii2[v]);
                st[i]            = cmul(st[i], flor2[v], floi2[v]);
            }
        }
    }

    // ---------- sign bits ----------
    const u32 SGE[4] = { (u32)l0 << 31, (u32)l1 << 31, (u32)l2 << 31, (u32)l3 << 31 };
    const u32 SA  = (u32)(l0 ^ l1) << 31;
    const u32 SB  = (u32)(l0 ^ l1 ^ l2) << 31;
    const u32 SC  = (u32)(l1 ^ l2 ^ l3) << 31;
    const u32 SD  = (u32)(l2 ^ l3) << 31;
    const u32 S4o = (u32)l3 << 31;
    const u32 S5o = (u32)l0 << 31;

#define MKCOEF(tval, sgn, TT, NT) do { \
        const float _te = __uint_as_float(__float_as_uint(tval) ^ (sgn)); \
        TT = pk2(_te, _te); NT = pk2(-_te, -_te); } while (0)

    // ---------- 4 layers: d=1,3 sigma'd (pe=0); d=2,4 plain (pe=1) ----------
#pragma unroll 1
    for (int dd = 0; dd < 2; dd++) {
        const float* To = T2 + (2 * dd) * 10;       // odd layer d=2dd+1
        const float* Te = T2 + (2 * dd + 1) * 10;   // even layer d=2dd+2
        u64 tt, nt;

        // odd layer, phase 1 (p=0 map: slot v gates bit v)
        MKCOEF(To[0], SA,  tt, nt); gate_slot_sig<0, 0x02>(st, tt, nt);
        MKCOEF(To[1], SB,  tt, nt); gate_slot_sig<1, 0x05>(st, tt, nt);
        MKCOEF(To[2], SC,  tt, nt); gate_slot_sig<2, 0x0A>(st, tt, nt);
        MKCOEF(To[3], SD,  tt, nt); gate_slot_sig<3, 0x14>(st, tt, nt);
        MKCOEF(To[4], S4o, tt, nt); gate_slot_sig<4, 0x28>(st, tt, nt);
        MKCOEF(To[5], S5o, tt, nt); gate_slot_sig<5, 0x10>(st, tt, nt);
        swap_fused(st);
        // odd layer, phase 2 (p=1 map: slot k gates bit 6+k)
        MKCOEF(To[6], SA, tt, nt); gate_slot_sig<0, 0x22>(st, tt, nt);
        MKCOEF(To[7], SB, tt, nt); gate_slot_sig<1, 0x05>(st, tt, nt);
        MKCOEF(To[8], SC, tt, nt); gate_slot_sig<2, 0x0A>(st, tt, nt);
        MKCOEF(To[9], SD, tt, nt); gate_slot_sig<3, 0x04>(st, tt, nt);

        // even layer (pe=1), phase 1: skew signs only
        MKCOEF(Te[0], SGE[0], tt, nt); gate_slot<0>(st, tt, nt);
        MKCOEF(Te[1], SGE[1], tt, nt); gate_slot<1>(st, tt, nt);
        MKCOEF(Te[2], SGE[2], tt, nt); gate_slot<2>(st, tt, nt);
        MKCOEF(Te[3], SGE[3], tt, nt); gate_slot<3>(st, tt, nt);
        MKCOEF(Te[4], 0u,     tt, nt); gate_slot<4>(st, tt, nt);
        MKCOEF(Te[5], 0u,     tt, nt); gate_slot<5>(st, tt, nt);
        swap_fused(st);
        MKCOEF(Te[6], SGE[0], tt, nt); gate_slot<0>(st, tt, nt);
        MKCOEF(Te[7], SGE[1], tt, nt); gate_slot<1>(st, tt, nt);
        MKCOEF(Te[8], SGE[2], tt, nt); gate_slot<2>(st, tt, nt);
        MKCOEF(Te[9], SGE[3], tt, nt); gate_slot<3>(st, tt, nt);
    }
#undef MKCOEF

    // ---------- folded layer 5: observables on the post-L4 state (p=0) ----------
    // pre-swap X partials: slot v <-> bit v <-> wire 9-v
    const float Xp0 = xslot<0, 0x02>(st);   // wire 9, neighbor b1
    const float Xp1 = xslot<1, 0x05>(st);   // wire 8, b0^b2
    const float Xp2 = xslot<2, 0x0A>(st);   // wire 7, b1^b3
    const float Xp3 = xslot<3, 0x14>(st);   // wire 6, b2^b4
    const float Xp4 = xslot<4, 0x28>(st);   // wire 5, b3^b5
    const float Xp5 = xslot<5, 0x10>(st);   // wire 4, b4^b6

    swap_fused(st);

    // post-swap (p=1): slot k <-> bit 6+k <-> wire 3-k
    const float Xq0 = xslot<0, 0x22>(st);   // wire 3, b5^b7
    const float Xq1 = xslot<1, 0x05>(st);   // wire 2, b6^b8
    const float Xq2 = xslot<2, 0x0A>(st);   // wire 1, b7^b9
    const float Xq3 = xslot<3, 0x04>(st);   // wire 0, b8

    // probabilities and marginals (packed accumulate)
    u64 ta = 0ull, m0 = 0ull, m1 = 0ull, m2 = 0ull, m3 = 0ull, m4 = 0ull, m5 = 0ull;
#pragma unroll
    for (int r = 0; r < 64; r++) {
        const u64 p2 = mul2(st[r], st[r]);
        ta = add2(ta, p2);
        if (r & 1)  m0 = add2(m0, p2);
        if (r & 2)  m1 = add2(m1, p2);
        if (r & 4)  m2 = add2(m2, p2);
        if (r & 8)  m3 = add2(m3, p2);
        if (r & 16) m4 = add2(m4, p2);
        if (r & 32) m5 = add2(m5, p2);
    }
    float t_all, tb[6];
    { float a, b; upk2(ta, a, b); t_all = a + b;
      upk2(m0, a, b); tb[0] = a + b;
      upk2(m1, a, b); tb[1] = a + b;
      upk2(m2, a, b); tb[2] = a + b;
      upk2(m3, a, b); tb[3] = a + b;
      upk2(m4, a, b); tb[4] = a + b;
      upk2(m5, a, b); tb[5] = a + b; }

    // lane parities for the sigma X terms
    const u32 pA = (u32)l1, pB = (u32)(l0 ^ l2), pC = (u32)(l1 ^ l3), pD = (u32)l2;

    float ex[10];
    // wires 9..6 (bits 0..3 = lane bits post-swap): Z = +/- t_all
    ex[9] = fmaf(c5sh[9], l0 ? -t_all : t_all, -sgnf(s5sh[9], pA) * Xp0);
    ex[8] = fmaf(c5sh[8], l1 ? -t_all : t_all, -sgnf(s5sh[8], pB) * Xp1);
    ex[7] = fmaf(c5sh[7], l2 ? -t_all : t_all, -sgnf(s5sh[7], pC) * Xp2);
    ex[6] = fmaf(c5sh[6], l3 ? -t_all : t_all, -sgnf(s5sh[6], pD) * Xp3);
    // wires 5,4 (bits 4,5 = r4,r5, unskewed)
    ex[5] = fmaf(c5sh[5], t_all - 2.0f * tb[4], -sgnf(s5sh[5], (u32)l3) * Xp4);
    ex[4] = fmaf(c5sh[4], t_all - 2.0f * tb[5], -sgnf(s5sh[4], (u32)l0) * Xp5);
    // wires 3..0 (bits 6..9 = slots 0..3 skewed)
    {
        const float z0 = t_all - 2.0f * tb[0];
        const float z1 = t_all - 2.0f * tb[1];
        const float z2 = t_all - 2.0f * tb[2];
        const float z3 = t_all - 2.0f * tb[3];
        ex[3] = fmaf(c5sh[3], l0 ? -z0 : z0, -sgnf(s5sh[3], pA) * Xq0);
        ex[2] = fmaf(c5sh[2], l1 ? -z1 : z1, -sgnf(s5sh[2], pB) * Xq1);
        ex[1] = fmaf(c5sh[1], l2 ? -z2 : z2, -sgnf(s5sh[1], pC) * Xq2);
        ex[0] = fmaf(c5sh[0], l3 ? -z3 : z3, -sgnf(s5sh[0], pD) * Xq3);
    }

    // packed reduce across the 16 lanes of this element
    u64 ep[5];
#pragma unroll
    for (int i = 0; i < 5; i++) ep[i] = pk2(ex[2 * i], ex[2 * i + 1]);
#pragma unroll
    for (int m = 8; m >= 1; m >>= 1) {
#pragma unroll
        for (int i = 0; i < 5; i++)
            ep[i] = add2(ep[i], __shfl_xor_sync(0xffffffffu, ep[i], m));
    }
    float exf[10];
#pragma unroll
    for (int i = 0; i < 5; i++) upk2(ep[i], exf[2 * i], exf[2 * i + 1]);

    // ---------- classifier head: each of 16 lanes emits one class ----------
    {
        float acc = bsh[l];
#pragma unroll
        for (int q2 = 0; q2 < 10; q2++)
            acc = fmaf(exf[q2], wsh[l * 10 + q2], acc);
        out[elem * 16 + l] = acc;
    }
}

extern "C" void kernel_launch(void* const* d_in, const int* in_sizes, int n_in,
                              void* d_out, int out_size)
{
    const float* x      = (const float*)d_in[0];  // (B, 10)
    const float* params = (const float*)d_in[1];  // (6, 10)
    const float* w_cls  = (const float*)d_in[2];  // (16, 10)
    const float* b_cls  = (const float*)d_in[3];  // (16,)
    float* out = (float*)d_out;

    const int B = in_sizes[0] / 10;
    const int elems_per_block = 8;                // 4 warps x 2 elements
    const int blocks = (B + elems_per_block - 1) / elems_per_block;
    qsim_kernel<<<blocks, 128>>>(x, params, w_cls, b_cls, out, B);
}

// round 16
// speedup vs baseline: 1.2206x; 1.0102x over previous
#include <cuda_runtime.h>

typedef unsigned long long u64;
typedef unsigned int u32;

// ---- packed f32x2 helpers (Blackwell sm_100a) ----
__device__ __forceinline__ u64 pk2(float lo, float hi) {
    u64 r; asm("mov.b64 %0, {%1, %2};" : "=l"(r) : "f"(lo), "f"(hi)); return r;
}
__device__ __forceinline__ void upk2(u64 v, float& lo, float& hi) {
    asm("mov.b64 {%0, %1}, %2;" : "=f"(lo), "=f"(hi) : "l"(v));
}
__device__ __forceinline__ u64 fma2(u64 a, u64 b, u64 c) {
    u64 r; asm("fma.rn.f32x2 %0, %1, %2, %3;" : "=l"(r) : "l"(a), "l"(b), "l"(c)); return r;
}
__device__ __forceinline__ u64 mul2(u64 a, u64 b) {
    u64 r; asm("mul.rn.f32x2 %0, %1, %2;" : "=l"(r) : "l"(a), "l"(b)); return r;
}
__device__ __forceinline__ u64 add2(u64 a, u64 b) {
    u64 r; asm("add.rn.f32x2 %0, %1, %2;" : "=l"(r) : "l"(a), "l"(b)); return r;
}
// packed complex multiply: z * w, with w pre-split as wr2=(re,re), wi2=(-im,im).
__device__ __forceinline__ u64 cmul(u64 z, u64 wr2, u64 wi2) {
    float zr, zi; upk2(z, zr, zi);
    return fma2(wi2, pk2(zi, zr), mul2(wr2, z));
}

#define PC6(v) ((((v)>>0)&1)+(((v)>>1)&1)+(((v)>>2)&1)+(((v)>>3)&1)+(((v)>>4)&1)+(((v)>>5)&1))

// 10-qubit register: wire w = flat-index bit (9-w); bit g <-> wire 9-g.
// 2 elements per warp; 16 lanes (l = lane&15) per element; 64 amps/thread.
// XOR-skewed storage: y_v = r_v ^ l_v (v<4); y_4 = r_4; y_5 = r_5.
// Parity p layouts:
//   p=0: local slot v <-> bit v ; lane slot u <-> bit 6+u
//   p=1: local slot v<4 <-> bit 6+v ; slots 4,5 <-> bits 4,5 ; lane u <-> bit u
// 4-bit lane<->local exchange = ONE shfl_xor per register (mask r&15).
//
// LAYER-0 FUSION: d=0 RY folded into init vectors u_w = RY_tan RX |0>.
// CZ conjugation: final = (D) L5^s L4 L3^s L2 L1^s psi0; outer D dies in probs.
// LAYER-5 FUSION: L5^s folded into observables:
//   ex_w = cos(t5_w) <Z_w> - sin(t5_w) <sigma X_w>  on the post-L4 state.
// Epilogue order (this round): Xp (p=0), probs/marginals (p=0 labels,
// shared-subtree partial sums), swap, Xq (p=1) — marginal FMA work overlaps
// the swap's shuffle latency; only Xq trails the swap.

template<int K>
__device__ __forceinline__ void gate_slot(u64 (&st)[64], u64 tt, u64 nt) {
#pragma unroll
    for (int w = 0; w < 32; w++) {
        const int i  = ((w >> K) << (K + 1)) | (w & ((1 << K) - 1));
        const int j2 = i | (1 << K);
        const u64 a0 = st[i], a1 = st[j2];
        st[i]  = fma2(nt, a1, a0);   // a0 - te*a1
        st[j2] = fma2(tt, a0, a1);   // a1 + te*a0
    }
}

template<int K, int RMASK>
__device__ __forceinline__ void gate_slot_sig(u64 (&st)[64], u64 tt, u64 nt) {
#pragma unroll
    for (int w = 0; w < 32; w++) {
        const int i  = ((w >> K) << (K + 1)) | (w & ((1 << K) - 1));
        const int j2 = i | (1 << K);
        const int neg = PC6(i & RMASK) & 1;            // compile-time
        const u64 a0 = st[i], a1 = st[j2];
        if (neg) {
            st[i]  = fma2(tt, a1, a0);
            st[j2] = fma2(nt, a0, a1);
        } else {
            st[i]  = fma2(nt, a1, a0);
            st[j2] = fma2(tt, a0, a1);
        }
    }
}

// X-expectation partial for local slot K with sigma register-parity RMASK.
template<int K, int RMASK>
__device__ __forceinline__ float xslot(const u64 (&st)[64]) {
    u64 xp = 0ull, xn = 0ull;
#pragma unroll
    for (int w = 0; w < 32; w++) {
        const int i  = ((w >> K) << (K + 1)) | (w & ((1 << K) - 1));
        const int j2 = i | (1 << K);
        if (PC6(i & RMASK) & 1) xn = fma2(st[i], st[j2], xn);
        else                    xp = fma2(st[i], st[j2], xp);
    }
    float pl, ph, nl, nh; upk2(xp, pl, ph); upk2(xn, nl, nh);
    return (pl + ph) - (nl + nh);
}

__device__ __forceinline__ void swap_fused(u64 (&st)[64]) {
#pragma unroll
    for (int r = 0; r < 64; r++) {
        const int m = r & 15;
        if (m)
            st[r] = __shfl_xor_sync(0xffffffffu, st[r], m);
    }
}

__device__ __forceinline__ float sgnf(float f, u32 par) {
    return __uint_as_float(__float_as_uint(f) ^ (par << 31));
}

__global__ __launch_bounds__(128, 3)
void qsim_kernel(const float* __restrict__ x,
                 const float* __restrict__ params,
                 const float* __restrict__ w_cls,
                 const float* __restrict__ b_cls,
                 float* __restrict__ out, int B)
{
    __shared__ float tsh[64], cwork[64], T2[48], wsh[160], bsh[16];
    __shared__ float c5sh[10], s5sh[10];
    __shared__ float Cprod_sh;
    const int tid = threadIdx.x;
    if (tid < 60) {
        float s, c;
        sincosf(params[tid] * 0.5f, &s, &c);
        tsh[tid] = s / c;          // tan(theta/2)
        cwork[tid] = c;
    }
    if (tid >= 96 && tid < 106) {  // layer-5 FULL-angle coefficients
        const int w = tid - 96;
        float s, c;
        sincosf(params[50 + w], &s, &c);
        c5sh[w] = c;
        s5sh[w] = 2.0f * s;        // X cross-terms carry the factor 2
    }
    for (int k = tid; k < 160; k += 128) wsh[k] = w_cls[k];
    if (tid < 16) bsh[tid] = b_cls[tid];
    __syncthreads();
    // T2 rows 0..3 <-> layers d=1..4; entry parity pe(d) = (d+1)&1
    if (tid < 40) {
        int row = tid / 10, k = tid % 10;
        int d = row + 1, pe = (d + 1) & 1;
        int wire;
        if (k < 6) wire = pe ? ((k < 4) ? 3 - k : 9 - k) : 9 - k;
        else { int j = k - 6; wire = pe ? 9 - j : 3 - j; }
        T2[tid] = tsh[d * 10 + wire];
    }
    if (tid == 0) {
        float pp = 1.0f;
        for (int k = 0; k < 50; k++) pp *= cwork[k];   // layers 0..4 only
        Cprod_sh = pp;
    }
    __syncthreads();
    const float Cprod = Cprod_sh;

    const int lane = tid & 31;
    const int l    = lane & 15;
    const int half = lane >> 4;
    const int elem = (blockIdx.x * (blockDim.x >> 5) + (tid >> 5)) * 2 + half;
    if (elem >= B) return;

    // ---------- init: product of u_w = RY_tan(t0_w) RX(x_w) |0>  ----------
    u64 cspack = 0;
    if (l < 10) {
        float s, c;
        sincosf(x[elem * 10 + l] * 0.5f, &s, &c);
        cspack = pk2(c, s);
    }
    float re0[10], im0[10], re1[10], im1[10];
#pragma unroll
    for (int q = 0; q < 10; q++) {
        float c, s;
        upk2(__shfl_sync(0xffffffffu, cspack, (lane & 16) + q), c, s);
        const float t0 = tsh[q];
        re0[q] = c;        im0[q] = t0 * s;
        re1[q] = t0 * c;   im1[q] = -s;
    }

    // lane product over bits 6..9 (p=0: bit 6+u = l_u, wire 3-u), scaled by Cprod
    const int l0 = (l >> 0) & 1, l1 = (l >> 1) & 1, l2 = (l >> 2) & 1, l3 = (l >> 3) & 1;
    u64 z = pk2(l0 ? re1[3] : re0[3], l0 ? im1[3] : im0[3]);
    {
        const int lb[3] = { l1, l2, l3 };
#pragma unroll
        for (int u = 1; u < 4; u++) {
            const int w = 3 - u;
            const float wre = lb[u - 1] ? re1[w] : re0[w];
            const float wim = lb[u - 1] ? im1[w] : im0[w];
            z = cmul(z, pk2(wre, wre), pk2(-wim, wim));
        }
        z = mul2(z, pk2(Cprod, Cprod));
    }

    // per-slot complex factors (skew-aware for v<4): slot v <-> bit v, wire 9-v
    u64 flor2[6], floi2[6], fhir2[6], fhii2[6];
#pragma unroll
    for (int v = 0; v < 6; v++) {
        const int w = 9 - v;
        const int lb = (v < 4) ? ((l >> v) & 1) : 0;
        const float lre = lb ? re1[w] : re0[w], lim = lb ? im1[w] : im0[w];
        const float hre = lb ? re0[w] : re1[w], him = lb ? im0[w] : im1[w];
        flor2[v] = pk2(lre, lre); floi2[v] = pk2(-lim, lim);
        fhir2[v] = pk2(hre, hre); fhii2[v] = pk2(-him, him);
    }

    // recursive complex tensor-product build (in place)
    u64 st[64];
    st[0] = z;
#pragma unroll
    for (int v = 0; v < 6; v++) {
#pragma unroll
        for (int i = 0; i < 32; i++) {
            if (i < (1 << v)) {
                st[i | (1 << v)] = cmul(st[i], fhir2[v], fhii2[v]);
                st[i]            = cmul(st[i], flor2[v], floi2[v]);
            }
        }
    }

    // ---------- sign bits ----------
    const u32 SGE[4] = { (u32)l0 << 31, (u32)l1 << 31, (u32)l2 << 31, (u32)l3 << 31 };
    const u32 SA  = (u32)(l0 ^ l1) << 31;
    const u32 SB  = (u32)(l0 ^ l1 ^ l2) << 31;
    const u32 SC  = (u32)(l1 ^ l2 ^ l3) << 31;
    const u32 SD  = (u32)(l2 ^ l3) << 31;
    const u32 S4o = (u32)l3 << 31;
    const u32 S5o = (u32)l0 << 31;

#define MKCOEF(tval, sgn, TT, NT) do { \
        const float _te = __uint_as_float(__float_as_uint(tval) ^ (sgn)); \
        TT = pk2(_te, _te); NT = pk2(-_te, -_te); } while (0)

    // ---------- 4 layers: d=1,3 sigma'd (pe=0); d=2,4 plain (pe=1) ----------
#pragma unroll 1
    for (int dd = 0; dd < 2; dd++) {
        const float* To = T2 + (2 * dd) * 10;       // odd layer d=2dd+1
        const float* Te = T2 + (2 * dd + 1) * 10;   // even layer d=2dd+2
        u64 tt, nt;

        // odd layer, phase 1 (p=0 map: slot v gates bit v)
        MKCOEF(To[0], SA,  tt, nt); gate_slot_sig<0, 0x02>(st, tt, nt);
        MKCOEF(To[1], SB,  tt, nt); gate_slot_sig<1, 0x05>(st, tt, nt);
        MKCOEF(To[2], SC,  tt, nt); gate_slot_sig<2, 0x0A>(st, tt, nt);
        MKCOEF(To[3], SD,  tt, nt); gate_slot_sig<3, 0x14>(st, tt, nt);
        MKCOEF(To[4], S4o, tt, nt); gate_slot_sig<4, 0x28>(st, tt, nt);
        MKCOEF(To[5], S5o, tt, nt); gate_slot_sig<5, 0x10>(st, tt, nt);
        swap_fused(st);
        // odd layer, phase 2 (p=1 map: slot k gates bit 6+k)
        MKCOEF(To[6], SA, tt, nt); gate_slot_sig<0, 0x22>(st, tt, nt);
        MKCOEF(To[7], SB, tt, nt); gate_slot_sig<1, 0x05>(st, tt, nt);
        MKCOEF(To[8], SC, tt, nt); gate_slot_sig<2, 0x0A>(st, tt, nt);
        MKCOEF(To[9], SD, tt, nt); gate_slot_sig<3, 0x04>(st, tt, nt);

        // even layer (pe=1), phase 1: skew signs only
        MKCOEF(Te[0], SGE[0], tt, nt); gate_slot<0>(st, tt, nt);
        MKCOEF(Te[1], SGE[1], tt, nt); gate_slot<1>(st, tt, nt);
        MKCOEF(Te[2], SGE[2], tt, nt); gate_slot<2>(st, tt, nt);
        MKCOEF(Te[3], SGE[3], tt, nt); gate_slot<3>(st, tt, nt);
        MKCOEF(Te[4], 0u,     tt, nt); gate_slot<4>(st, tt, nt);
        MKCOEF(Te[5], 0u,     tt, nt); gate_slot<5>(st, tt, nt);
        swap_fused(st);
        MKCOEF(Te[6], SGE[0], tt, nt); gate_slot<0>(st, tt, nt);
        MKCOEF(Te[7], SGE[1], tt, nt); gate_slot<1>(st, tt, nt);
        MKCOEF(Te[8], SGE[2], tt, nt); gate_slot<2>(st, tt, nt);
        MKCOEF(Te[9], SGE[3], tt, nt); gate_slot<3>(st, tt, nt);
    }
#undef MKCOEF

    // ---------- folded layer 5: observables on the post-L4 state ----------
    // pre-swap X partials (p=0): slot v <-> bit v <-> wire 9-v
    const float Xp0 = xslot<0, 0x02>(st);   // wire 9, neighbor b1
    const float Xp1 = xslot<1, 0x05>(st);   // wire 8, b0^b2
    const float Xp2 = xslot<2, 0x0A>(st);   // wire 7, b1^b3
    const float Xp3 = xslot<3, 0x14>(st);   // wire 6, b2^b4
    const float Xp4 = xslot<4, 0x28>(st);   // wire 5, b3^b5
    const float Xp5 = xslot<5, 0x10>(st);   // wire 4, b4^b6

    // probs/marginals PRE-swap (p=0 labels), shared-subtree partial sums
    u64 ta = 0ull, m0 = 0ull, m1 = 0ull, m2 = 0ull, m3 = 0ull, m4 = 0ull, m5 = 0ull;
#pragma unroll
    for (int g = 0; g < 16; g++) {
        const int r = 4 * g;
        const u64 p0 = mul2(st[r],     st[r]);
        const u64 p1 = mul2(st[r + 1], st[r + 1]);
        const u64 p2 = mul2(st[r + 2], st[r + 2]);
        const u64 p3 = mul2(st[r + 3], st[r + 3]);
        const u64 s01 = add2(p0, p1), s23 = add2(p2, p3);
        const u64 s4g = add2(s01, s23);
        ta = add2(ta, s4g);
        m0 = add2(m0, add2(p1, p3));
        m1 = add2(m1, s23);
        if (r & 4)  m2 = add2(m2, s4g);
        if (r & 8)  m3 = add2(m3, s4g);
        if (r & 16) m4 = add2(m4, s4g);
        if (r & 32) m5 = add2(m5, s4g);
    }
    float t_all, tb[6];
    { float a, b; upk2(ta, a, b); t_all = a + b;
      upk2(m0, a, b); tb[0] = a + b;
      upk2(m1, a, b); tb[1] = a + b;
      upk2(m2, a, b); tb[2] = a + b;
      upk2(m3, a, b); tb[3] = a + b;
      upk2(m4, a, b); tb[4] = a + b;
      upk2(m5, a, b); tb[5] = a + b; }

    swap_fused(st);

    // post-swap X partials (p=1): slot k <-> bit 6+k <-> wire 3-k
    const float Xq0 = xslot<0, 0x22>(st);   // wire 3, b5^b7
    const float Xq1 = xslot<1, 0x05>(st);   // wire 2, b6^b8
    const float Xq2 = xslot<2, 0x0A>(st);   // wire 1, b7^b9
    const float Xq3 = xslot<3, 0x04>(st);   // wire 0, b8

    // lane parities for the sigma X terms
    const u32 pA = (u32)l1, pB = (u32)(l0 ^ l2), pC = (u32)(l1 ^ l3), pD = (u32)l2;

    float ex[10];
    // wires 9..6: pre-swap bit v = slot v (skew l_v): Z = +/-(t_all - 2 tb_v)
    {
        const float z0 = t_all - 2.0f * tb[0];
        const float z1 = t_all - 2.0f * tb[1];
        const float z2 = t_all - 2.0f * tb[2];
        const float z3 = t_all - 2.0f * tb[3];
        ex[9] = fmaf(c5sh[9], l0 ? -z0 : z0, -sgnf(s5sh[9], pA) * Xp0);
        ex[8] = fmaf(c5sh[8], l1 ? -z1 : z1, -sgnf(s5sh[8], pB) * Xp1);
        ex[7] = fmaf(c5sh[7], l2 ? -z2 : z2, -sgnf(s5sh[7], pC) * Xp2);
        ex[6] = fmaf(c5sh[6], l3 ? -z3 : z3, -sgnf(s5sh[6], pD) * Xp3);
    }
    // wires 5,4: bits 4,5 (unskewed register bits — swap-invariant)
    ex[5] = fmaf(c5sh[5], t_all - 2.0f * tb[4], -sgnf(s5sh[5], (u32)l3) * Xp4);
    ex[4] = fmaf(c5sh[4], t_all - 2.0f * tb[5], -sgnf(s5sh[4], (u32)l0) * Xp5);
    // wires 3..0: pre-swap bits 6+k = lane bits: Z = +/- t_all
    ex[3] = fmaf(c5sh[3], l0 ? -t_all : t_all, -sgnf(s5sh[3], pA) * Xq0);
    ex[2] = fmaf(c5sh[2], l1 ? -t_all : t_all, -sgnf(s5sh[2], pB) * Xq1);
    ex[1] = fmaf(c5sh[1], l2 ? -t_all : t_all, -sgnf(s5sh[1], pC) * Xq2);
    ex[0] = fmaf(c5sh[0], l3 ? -t_all : t_all, -sgnf(s5sh[0], pD) * Xq3);

    // packed reduce across the 16 lanes of this element
    u64 ep[5];
#pragma unroll
    for (int i = 0; i < 5; i++) ep[i] = pk2(ex[2 * i], ex[2 * i + 1]);
#pragma unroll
    for (int m = 8; m >= 1; m >>= 1) {
#pragma unroll
        for (int i = 0; i < 5; i++)
            ep[i] = add2(ep[i], __shfl_xor_sync(0xffffffffu, ep[i], m));
    }
    float exf[10];
#pragma unroll
    for (int i = 0; i < 5; i++) upk2(ep[i], exf[2 * i], exf[2 * i + 1]);

    // ---------- classifier head: each of 16 lanes emits one class ----------
    {
        float acc = bsh[l];
#pragma unroll
        for (int q2 = 0; q2 < 10; q2++)
            acc = fmaf(exf[q2], wsh[l * 10 + q2], acc);
        out[elem * 16 + l] = acc;
    }
}

extern "C" void kernel_launch(void* const* d_in, const int* in_sizes, int n_in,
                              void* d_out, int out_size)
{
    const float* x      = (const float*)d_in[0];  // (B, 10)
    const float* params = (const float*)d_in[1];  // (6, 10)
    const float* w_cls  = (const float*)d_in[2];  // (16, 10)
    const float* b_cls  = (const float*)d_in[3];  // (16,)
    float* out = (float*)d_out;

    const int B = in_sizes[0] / 10;
    const int elems_per_block = 8;                // 4 warps x 2 elements
    const int blocks = (B + elems_per_block - 1) / elems_per_block;
    qsim_kernel<<<blocks, 128>>>(x, params, w_cls, b_cls, out, B);
}